// round 8
// baseline (speedup 1.0000x reference)
#include <cuda_runtime.h>
#include <cuda_bf16.h>
#include <math.h>
#include <cstdint>

using bf16 = __nv_bfloat16;

static constexpr int L_ = 6, D_ = 1024, H_ = 16, F_ = 4096, S_ = 512, B_ = 16, P_ = 512;
static constexpr int DH_ = D_ / H_;          // 64
static constexpr int M_ = B_ * S_;           // 8192
static constexpr int D3 = 3 * D_;            // 3072 (fused qkv width)

// ---------------- scratch (device globals; no allocations allowed) ----------
__device__ __align__(16) float g_h[(size_t)M_ * D_];
__device__ __align__(16) float g_out1[(size_t)M_ * D_];

__device__ __align__(16) bf16 g_xn_h[(size_t)M_ * D_];
__device__ __align__(16) bf16 g_xn_l[(size_t)M_ * D_];
__device__ __align__(16) bf16 g_qkv_h[(size_t)M_ * D3];
__device__ __align__(16) bf16 g_qkv_l[(size_t)M_ * D3];
__device__ __align__(16) bf16 g_ctx_h[(size_t)M_ * D_];
__device__ __align__(16) bf16 g_ctx_l[(size_t)M_ * D_];
__device__ __align__(16) bf16 g_f1_h[(size_t)M_ * F_];
__device__ __align__(16) bf16 g_f1_l[(size_t)M_ * F_];

// transposed+split weights: [N,K] bf16 (qkv fused: rows 0..1023=q, ..k, ..v)
__device__ __align__(16) bf16 g_wqkvT_h[(size_t)L_ * D3 * D_];
__device__ __align__(16) bf16 g_wqkvT_l[(size_t)L_ * D3 * D_];
__device__ __align__(16) bf16 g_woT_h[(size_t)L_ * D_ * D_];
__device__ __align__(16) bf16 g_woT_l[(size_t)L_ * D_ * D_];
__device__ __align__(16) bf16 g_w1T_h[(size_t)L_ * D_ * F_];
__device__ __align__(16) bf16 g_w1T_l[(size_t)L_ * D_ * F_];
__device__ __align__(16) bf16 g_w2T_h[(size_t)L_ * F_ * D_];
__device__ __align__(16) bf16 g_w2T_l[(size_t)L_ * F_ * D_];
__device__ __align__(16) float g_bqkv[(size_t)L_ * D3];

// ---------------- PTX helpers (sm_80-era, legal on plain sm_103) -------------
__device__ __forceinline__ uint32_t smem_u32(const void* p) {
    uint32_t a;
    asm("{ .reg .u64 t; cvta.to.shared.u64 t, %1; cvt.u32.u64 %0, t; }" : "=r"(a) : "l"(p));
    return a;
}
__device__ __forceinline__ void ldsm4(uint32_t* r, uint32_t addr) {
    asm volatile("ldmatrix.sync.aligned.m8n8.x4.shared.b16 {%0,%1,%2,%3}, [%4];"
                 : "=r"(r[0]), "=r"(r[1]), "=r"(r[2]), "=r"(r[3]) : "r"(addr));
}
__device__ __forceinline__ void ldsm4t(uint32_t* r, uint32_t addr) {
    asm volatile("ldmatrix.sync.aligned.m8n8.x4.trans.shared.b16 {%0,%1,%2,%3}, [%4];"
                 : "=r"(r[0]), "=r"(r[1]), "=r"(r[2]), "=r"(r[3]) : "r"(addr));
}
__device__ __forceinline__ void mma16816(float* d, const uint32_t* a, uint32_t b0, uint32_t b1) {
    asm volatile("mma.sync.aligned.m16n8k16.row.col.f32.bf16.bf16.f32 "
                 "{%0,%1,%2,%3}, {%4,%5,%6,%7}, {%8,%9}, {%0,%1,%2,%3};"
                 : "+f"(d[0]), "+f"(d[1]), "+f"(d[2]), "+f"(d[3])
                 : "r"(a[0]), "r"(a[1]), "r"(a[2]), "r"(a[3]), "r"(b0), "r"(b1));
}
#define CPA(dst, src)  asm volatile("cp.async.cg.shared.global [%0], [%1], 16;" :: "r"(dst), "l"(src))
#define CPA_COMMIT()   asm volatile("cp.async.commit_group;" ::: "memory")
#define CPA_WAIT1()    asm volatile("cp.async.wait_group 1;" ::: "memory")
#define CPA_WAIT0()    asm volatile("cp.async.wait_group 0;" ::: "memory")

__device__ __forceinline__ uint32_t swz(uint32_t off)   { return off ^ ((off >> 3) & 0x70); }
__device__ __forceinline__ uint32_t swz64(uint32_t off) { return off ^ ((off >> 3) & 0x30); }
__device__ __forceinline__ uint32_t smx(uint32_t row_byte, uint32_t col_byte) {
    return row_byte + (col_byte ^ ((row_byte >> 3) & 0x70));
}
__device__ __forceinline__ uint32_t smx64(uint32_t row_byte, uint32_t col_byte) {
    return row_byte + (col_byte ^ ((row_byte >> 3) & 0x30));
}

// ---------------- h = x + pe -------------------------------------------------
__global__ __launch_bounds__(256) void addpe_kernel(const float* __restrict__ x,
                                                    const float* __restrict__ pe,
                                                    float* __restrict__ h) {
    int i = blockIdx.x * 256 + threadIdx.x;
    h[i] = x[i] + pe[i & (S_ * D_ - 1)];
}

// ---------------- pack qkv bias: [L,3072] -------------------------------------
__global__ __launch_bounds__(256) void packb_kernel(const float* __restrict__ bq,
                                                    const float* __restrict__ bk,
                                                    const float* __restrict__ bv,
                                                    float* __restrict__ o) {
    int l = blockIdx.y;
    int i = blockIdx.x * 256 + threadIdx.x;
    o[(size_t)l * D3 + i]            = bq[l * D_ + i];
    o[(size_t)l * D3 + D_ + i]       = bk[l * D_ + i];
    o[(size_t)l * D3 + 2 * D_ + i]   = bv[l * D_ + i];
}

// ---------------- weight transpose + bf16 split: W[K,N] -> T[N,K] hi/lo -----
__global__ __launch_bounds__(256) void wtrans_kernel(const float* __restrict__ W,
                                                     bf16* __restrict__ Th,
                                                     bf16* __restrict__ Tl,
                                                     int K, int N, size_t out_ls) {
    __shared__ float t[32][33];
    size_t inoff  = (size_t)blockIdx.z * K * N;
    size_t outoff = (size_t)blockIdx.z * out_ls;
    int k0 = blockIdx.y * 32, n0 = blockIdx.x * 32;
    int tx = threadIdx.x & 31, ty = threadIdx.x >> 5;
#pragma unroll
    for (int i = 0; i < 32; i += 8)
        t[ty + i][tx] = W[inoff + (size_t)(k0 + ty + i) * N + n0 + tx];
    __syncthreads();
#pragma unroll
    for (int i = 0; i < 32; i += 8) {
        float v = t[tx][ty + i];
        bf16 hi = __float2bfloat16(v);
        size_t idx = outoff + (size_t)(n0 + ty + i) * K + k0 + tx;
        Th[idx] = hi;
        Tl[idx] = __float2bfloat16(v - __bfloat162float(hi));
    }
}

// ---------------- LayerNorm: fp32 in -> bf16 hi/lo out -----------------------
__global__ __launch_bounds__(256) void ln_kernel(const float* __restrict__ x,
                                                 const float* __restrict__ g,
                                                 const float* __restrict__ b,
                                                 bf16* __restrict__ yh,
                                                 bf16* __restrict__ yl) {
    int row = blockIdx.x, tid = threadIdx.x;
    const float* xr = x + (size_t)row * D_;
    float4 f = *(const float4*)(xr + tid * 4);
    float s  = f.x + f.y + f.z + f.w;
    float ss = f.x * f.x + f.y * f.y + f.z * f.z + f.w * f.w;
#pragma unroll
    for (int o = 16; o > 0; o >>= 1) {
        s  += __shfl_xor_sync(0xffffffffu, s, o);
        ss += __shfl_xor_sync(0xffffffffu, ss, o);
    }
    __shared__ float rs[8], rss[8];
    if ((tid & 31) == 0) { rs[tid >> 5] = s; rss[tid >> 5] = ss; }
    __syncthreads();
    float ts = 0.f, tss = 0.f;
#pragma unroll
    for (int i = 0; i < 8; i++) { ts += rs[i]; tss += rss[i]; }
    float mean = ts * (1.0f / D_);
    float var  = tss * (1.0f / D_) - mean * mean;
    float r    = rsqrtf(var + 1e-6f);
    float4 g4 = *(const float4*)(g + tid * 4);
    float4 b4 = *(const float4*)(b + tid * 4);
    float o[4];
    o[0] = (f.x - mean) * r * g4.x + b4.x;
    o[1] = (f.y - mean) * r * g4.y + b4.y;
    o[2] = (f.z - mean) * r * g4.z + b4.z;
    o[3] = (f.w - mean) * r * g4.w + b4.w;
    size_t base = (size_t)row * D_ + tid * 4;
#pragma unroll
    for (int j = 0; j < 4; j += 2) {
        bf16 h0 = __float2bfloat16(o[j]);
        bf16 h1 = __float2bfloat16(o[j + 1]);
        *(__nv_bfloat162*)(yh + base + j) = __nv_bfloat162(h0, h1);
        *(__nv_bfloat162*)(yl + base + j) = __nv_bfloat162(
            __float2bfloat16(o[j] - __bfloat162float(h0)),
            __float2bfloat16(o[j + 1] - __bfloat162float(h1)));
    }
}

// ---------------- split-bf16 mma.sync GEMM 128x128, Kc=32, SW64, x3, occ2 ---
static constexpr int TILE32 = 128 * 32 * 2;     // 8 KB per matrix tile
static constexpr int S_AH = 0, S_AL = TILE32, S_BH = 2 * TILE32, S_BL = 3 * TILE32;
static constexpr int STAGEB = 4 * TILE32;       // 32 KB per stage
static constexpr int GEMM_SMEM = 3 * STAGEB;    // 96 KB -> 2 CTAs/SM

__device__ __forceinline__ void tile_cpa32(const bf16* __restrict__ g,
                                           int row0, int stride, int k0,
                                           uint32_t sdst, int tid) {
#pragma unroll
    for (int i = 0; i < 2; i++) {
        int idx = i * 256 + tid;        // 0..511
        int r = idx >> 2, c = idx & 3;
        const bf16* src = g + (size_t)(row0 + r) * stride + k0 + c * 8;
        CPA(sdst + swz64(r * 64 + c * 16), src);
    }
}

__global__ __launch_bounds__(256, 2) void gemm_mma_kernel(
    const bf16* __restrict__ Ah, const bf16* __restrict__ Al,
    const bf16* __restrict__ Bh, const bf16* __restrict__ Bl,
    const float* __restrict__ bias, const float* __restrict__ r1,
    const float* __restrict__ r2, float* __restrict__ C,
    bf16* __restrict__ Ch, bf16* __restrict__ Cl,
    int NN, int KK, int act) {
    extern __shared__ char smem[];
    const uint32_t sb = smem_u32(smem);
    const int tid = threadIdx.x;
    const int wid = tid >> 5, lane = tid & 31;
    const int wm = wid >> 2, wn = wid & 3;
    const int rowBase = blockIdx.y * 128, colBase = blockIdx.x * 128;

    float acc[4][4][4];
#pragma unroll
    for (int i = 0; i < 4; i++)
#pragma unroll
        for (int j = 0; j < 4; j++)
#pragma unroll
            for (int q = 0; q < 4; q++) acc[i][j][q] = 0.f;

    // ldmatrix lane addressing (64-byte rows, SW64)
    const uint32_t a_row = (uint32_t)((wm * 64 + (lane & 15)) * 64);
    const uint32_t a_col = (uint32_t)((lane >> 4) * 16);
    const uint32_t b_row0 = (uint32_t)((wn * 32 + (lane & 7) + ((lane >> 4) << 3)) * 64);
    const uint32_t b_col = (uint32_t)(((lane >> 3) & 1) * 16);

    const int nc = KK / 32;
    // prologue: stages 0,1
    tile_cpa32(Ah, rowBase, KK, 0, sb + S_AH, tid);
    tile_cpa32(Al, rowBase, KK, 0, sb + S_AL, tid);
    tile_cpa32(Bh, colBase, KK, 0, sb + S_BH, tid);
    tile_cpa32(Bl, colBase, KK, 0, sb + S_BL, tid);
    CPA_COMMIT();
    {
        uint32_t st = sb + STAGEB;
        tile_cpa32(Ah, rowBase, KK, 32, st + S_AH, tid);
        tile_cpa32(Al, rowBase, KK, 32, st + S_AL, tid);
        tile_cpa32(Bh, colBase, KK, 32, st + S_BH, tid);
        tile_cpa32(Bl, colBase, KK, 32, st + S_BL, tid);
    }
    CPA_COMMIT();

    for (int c = 0; c < nc; c++) {
        if (c + 1 < nc) CPA_WAIT1(); else CPA_WAIT0();
        __syncthreads();
        if (c + 2 < nc) {
            uint32_t st = sb + ((c + 2) % 3) * STAGEB;
            int k0 = (c + 2) * 32;
            tile_cpa32(Ah, rowBase, KK, k0, st + S_AH, tid);
            tile_cpa32(Al, rowBase, KK, k0, st + S_AL, tid);
            tile_cpa32(Bh, colBase, KK, k0, st + S_BH, tid);
            tile_cpa32(Bl, colBase, KK, k0, st + S_BL, tid);
            CPA_COMMIT();
        }
        uint32_t st = sb + (c % 3) * STAGEB;

#pragma unroll
        for (int ks = 0; ks < 2; ks++) {
            const uint32_t kb = ks * 32;     // 16 bf16 = 32 bytes per k-step
            uint32_t bh[2][4], bl[2][4];
#pragma unroll
            for (int g = 0; g < 2; g++) {
                uint32_t roff = b_row0 + (uint32_t)(g * 16 * 64);
                ldsm4(bh[g], st + S_BH + smx64(roff, kb + b_col));
                ldsm4(bl[g], st + S_BL + smx64(roff, kb + b_col));
            }
#pragma unroll
            for (int mi = 0; mi < 4; mi++) {
                uint32_t roff = a_row + (uint32_t)(mi * 16 * 64);
                uint32_t a_h[4], a_l[4];
                ldsm4(a_h, st + S_AH + smx64(roff, kb + a_col));
                ldsm4(a_l, st + S_AL + smx64(roff, kb + a_col));
#pragma unroll
                for (int nj = 0; nj < 4; nj++) {
                    int g = nj >> 1, o = (nj & 1) * 2;
                    uint32_t h0 = bh[g][o], h1 = bh[g][o + 1];
                    uint32_t l0 = bl[g][o], l1 = bl[g][o + 1];
                    mma16816(acc[mi][nj], a_h, h0, h1);
                    mma16816(acc[mi][nj], a_h, l0, l1);
                    mma16816(acc[mi][nj], a_l, h0, h1);
                }
            }
        }
    }

    const int tq = lane >> 2, tr = lane & 3;
#pragma unroll
    for (int mi = 0; mi < 4; mi++) {
#pragma unroll
        for (int nj = 0; nj < 4; nj++) {
            int n = colBase + wn * 32 + nj * 8 + tr * 2;
            float2 bb = *(const float2*)(bias + n);
#pragma unroll
            for (int half = 0; half < 2; half++) {
                int m = rowBase + wm * 64 + mi * 16 + tq + half * 8;
                size_t base = (size_t)m * NN + n;
                float v0 = acc[mi][nj][half * 2 + 0] + bb.x;
                float v1 = acc[mi][nj][half * 2 + 1] + bb.y;
                if (act == 1) { v0 = v0 * normcdff(v0); v1 = v1 * normcdff(v1); }
                if (r1) { float2 q = *(const float2*)(r1 + base); v0 += q.x; v1 += q.y; }
                if (r2) { float2 q = *(const float2*)(r2 + base); v0 += q.x; v1 += q.y; }
                if (C) { float2 ov = {v0, v1}; *(float2*)(C + base) = ov; }
                if (Ch) {
                    bf16 h0 = __float2bfloat16(v0);
                    bf16 h1 = __float2bfloat16(v1);
                    *(__nv_bfloat162*)(Ch + base) = __nv_bfloat162(h0, h1);
                    *(__nv_bfloat162*)(Cl + base) = __nv_bfloat162(
                        __float2bfloat16(v0 - __bfloat162float(h0)),
                        __float2bfloat16(v1 - __bfloat162float(h1)));
                }
            }
        }
    }
}

// ---------------- tensor-core attention (reads fused qkv buffer) ------------
static constexpr int QT = 32;
static constexpr int SCS2 = 520;
static constexpr int AO_Q   = 0;
static constexpr int AO_KV  = 8192;
static constexpr int AO_SC  = 40960;
static constexpr int AO_AWH = 107520;
static constexpr int AO_AWL = 140800;
static constexpr int ATTN_SMEM = 174080;

__device__ __forceinline__ void tile64_cpa(const bf16* __restrict__ g,
                                           int row0, int stride,
                                           uint32_t sdst, int tid) {
#pragma unroll
    for (int i = 0; i < 2; i++) {
        int idx = i * 256 + tid;
        int r = idx >> 3, c = idx & 7;
        CPA(sdst + swz(r * 128 + c * 16), g + (size_t)(row0 + r) * stride + c * 8);
    }
}

__global__ __launch_bounds__(256, 1) void attn_mma_kernel(
    const bf16* __restrict__ qkvh, const bf16* __restrict__ qkvl,
    const float* __restrict__ bias,
    bf16* __restrict__ Ch, bf16* __restrict__ Cl) {
    extern __shared__ char smem[];
    const uint32_t sb = smem_u32(smem);
    const int tid = threadIdx.x;
    const int wid = tid >> 5, lane = tid & 31;
    const int wm = wid >> 2, wn = wid & 3;
    const int q0 = blockIdx.x * QT, h = blockIdx.y, b = blockIdx.z;
    const size_t base3 = (size_t)(b * S_) * D3 + h * DH_;
    const bf16* Qh = qkvh + base3;            const bf16* Ql = qkvl + base3;
    const bf16* Kh = qkvh + base3 + D_;       const bf16* Kl = qkvl + base3 + D_;
    const bf16* Vh = qkvh + base3 + 2 * D_;   const bf16* Vl = qkvl + base3 + 2 * D_;
    const int tq = lane >> 2, tr = lane & 3;

    {
        int r = tid >> 3, c = tid & 7;
        CPA(sb + AO_Q + swz(r * 128 + c * 16),        Qh + (size_t)(q0 + r) * D3 + c * 8);
        CPA(sb + AO_Q + 4096 + swz(r * 128 + c * 16), Ql + (size_t)(q0 + r) * D3 + c * 8);
    }
    tile64_cpa(Kh, 0, D3, sb + AO_KV, tid);
    tile64_cpa(Kl, 0, D3, sb + AO_KV + 8192, tid);
    CPA_COMMIT();
    CPA_WAIT0();
    __syncthreads();

    uint32_t qfh[4][4], qfl[4][4];
    {
        uint32_t arow = (uint32_t)((wm * 16 + (lane & 15)) * 128);
        uint32_t acol = (uint32_t)((lane >> 4) * 16);
#pragma unroll
        for (int ks = 0; ks < 4; ks++) {
            ldsm4(qfh[ks], sb + AO_Q + smx(arow, ks * 32 + acol));
            ldsm4(qfl[ks], sb + AO_Q + 4096 + smx(arow, ks * 32 + acol));
        }
    }

    const uint32_t b_row = (uint32_t)((wn * 16 + (lane & 7) + ((lane >> 4) << 3)) * 128);
    const uint32_t b_col = (uint32_t)(((lane >> 3) & 1) * 16);
    for (int c = 0; c < 8; c++) {
        if (c < 7) {
            uint32_t st = sb + AO_KV + ((c + 1) & 1) * 16384;
            tile64_cpa(Kh, (c + 1) * 64, D3, st, tid);
            tile64_cpa(Kl, (c + 1) * 64, D3, st + 8192, tid);
            CPA_COMMIT();
            CPA_WAIT1();
        } else {
            CPA_WAIT0();
        }
        __syncthreads();
        uint32_t st = sb + AO_KV + (c & 1) * 16384;

        float acc[2][4] = {};
#pragma unroll
        for (int ks = 0; ks < 4; ks++) {
            uint32_t cb = ks * 32 + b_col;
            uint32_t kh4[4], kl4[4];
            ldsm4(kh4, st + smx(b_row, cb));
            ldsm4(kl4, st + 8192 + smx(b_row, cb));
#pragma unroll
            for (int nj = 0; nj < 2; nj++) {
                mma16816(acc[nj], qfh[ks], kh4[nj * 2], kh4[nj * 2 + 1]);
                mma16816(acc[nj], qfh[ks], kl4[nj * 2], kl4[nj * 2 + 1]);
                mma16816(acc[nj], qfl[ks], kh4[nj * 2], kh4[nj * 2 + 1]);
            }
        }
        float* sc = (float*)(smem + AO_SC);
#pragma unroll
        for (int nj = 0; nj < 2; nj++) {
            int kg = c * 64 + wn * 16 + nj * 8 + tr * 2;
#pragma unroll
            for (int half = 0; half < 2; half++) {
                int m = wm * 16 + tq + half * 8;
                int rel = (q0 + m) - kg + (P_ - 1);
                sc[m * SCS2 + kg]     = acc[nj][half * 2 + 0] * 0.125f + __ldg(&bias[rel * H_ + h]);
                sc[m * SCS2 + kg + 1] = acc[nj][half * 2 + 1] * 0.125f + __ldg(&bias[(rel - 1) * H_ + h]);
            }
        }
        __syncthreads();
    }

    tile64_cpa(Vh, 0, D3, sb + AO_KV, tid);
    tile64_cpa(Vl, 0, D3, sb + AO_KV + 8192, tid);
    CPA_COMMIT();

    {
        float* sc = (float*)(smem + AO_SC);
        bf16* awh = (bf16*)(smem + AO_AWH);
        bf16* awl = (bf16*)(smem + AO_AWL);
#pragma unroll
        for (int rr = 0; rr < 4; rr++) {
            int r = wid * 4 + rr;
            float* row = sc + r * SCS2;
            float mx = -1e30f;
            for (int cc = lane; cc < S_; cc += 32) mx = fmaxf(mx, row[cc]);
#pragma unroll
            for (int o = 16; o > 0; o >>= 1) mx = fmaxf(mx, __shfl_xor_sync(0xffffffffu, mx, o));
            float sum = 0.f;
            for (int cc = lane; cc < S_; cc += 32) {
                float e = expf(row[cc] - mx);
                row[cc] = e;
                sum += e;
            }
#pragma unroll
            for (int o = 16; o > 0; o >>= 1) sum += __shfl_xor_sync(0xffffffffu, sum, o);
            float inv = 1.0f / sum;
            for (int cc = lane; cc < S_; cc += 32) {
                float a = row[cc] * inv;
                bf16 hi = __float2bfloat16(a);
                awh[r * SCS2 + cc] = hi;
                awl[r * SCS2 + cc] = __float2bfloat16(a - __bfloat162float(hi));
            }
        }
    }
    __syncthreads();

    float cacc[2][4] = {};
    const uint32_t aw_row = (uint32_t)((wm * 16 + (lane & 15)) * (SCS2 * 2));
    const uint32_t v_row = (uint32_t)(((lane & 7) + ((lane >> 3) & 1) * 8) * 128);
    const uint32_t v_col = (uint32_t)(wn * 32 + (lane >> 4) * 16);
    for (int c = 0; c < 8; c++) {
        if (c < 7) {
            uint32_t st = sb + AO_KV + ((c + 1) & 1) * 16384;
            tile64_cpa(Vh, (c + 1) * 64, D3, st, tid);
            tile64_cpa(Vl, (c + 1) * 64, D3, st + 8192, tid);
            CPA_COMMIT();
            CPA_WAIT1();
        } else {
            CPA_WAIT0();
        }
        __syncthreads();
        uint32_t st = sb + AO_KV + (c & 1) * 16384;

#pragma unroll
        for (int ks = 0; ks < 4; ks++) {
            uint32_t awoff = aw_row + (uint32_t)((c * 64 + ks * 16 + (lane >> 4) * 8) * 2);
            uint32_t ah4[4], al4[4];
            ldsm4(ah4, sb + AO_AWH + awoff);
            ldsm4(al4, sb + AO_AWL + awoff);
            uint32_t vro = v_row + (uint32_t)(ks * 16 * 128);
            uint32_t vh4[4], vl4[4];
            ldsm4t(vh4, st + smx(vro, v_col));
            ldsm4t(vl4, st + 8192 + smx(vro, v_col));
#pragma unroll
            for (int nj = 0; nj < 2; nj++) {
                mma16816(cacc[nj], ah4, vh4[nj * 2], vh4[nj * 2 + 1]);
                mma16816(cacc[nj], ah4, vl4[nj * 2], vl4[nj * 2 + 1]);
                mma16816(cacc[nj], al4, vh4[nj * 2], vh4[nj * 2 + 1]);
            }
        }
        __syncthreads();
    }

#pragma unroll
    for (int nj = 0; nj < 2; nj++) {
        int n = wn * 16 + nj * 8 + tr * 2;
#pragma unroll
        for (int half = 0; half < 2; half++) {
            int m = wm * 16 + tq + half * 8;
            size_t gidx = (size_t)(b * S_ + q0 + m) * D_ + h * DH_ + n;
            float v0 = cacc[nj][half * 2 + 0];
            float v1 = cacc[nj][half * 2 + 1];
            bf16 h0 = __float2bfloat16(v0);
            bf16 h1 = __float2bfloat16(v1);
            *(__nv_bfloat162*)(Ch + gidx) = __nv_bfloat162(h0, h1);
            *(__nv_bfloat162*)(Cl + gidx) = __nv_bfloat162(
                __float2bfloat16(v0 - __bfloat162float(h0)),
                __float2bfloat16(v1 - __bfloat162float(h1)));
        }
    }
}

// ---------------- launch ----------------------------------------------------
extern "C" void kernel_launch(void* const* d_in, const int* in_sizes, int n_in,
                              void* d_out, int out_size) {
    (void)in_sizes; (void)n_in; (void)out_size;
    const float* x    = (const float*)d_in[0];
    const float* pe   = (const float*)d_in[1];
    const float* wq   = (const float*)d_in[2];
    const float* bq   = (const float*)d_in[3];
    const float* wk   = (const float*)d_in[4];
    const float* bk   = (const float*)d_in[5];
    const float* wv   = (const float*)d_in[6];
    const float* bv   = (const float*)d_in[7];
    const float* wo   = (const float*)d_in[8];
    const float* bo   = (const float*)d_in[9];
    const float* bt   = (const float*)d_in[10];
    const float* w1   = (const float*)d_in[11];
    const float* b1   = (const float*)d_in[12];
    const float* w2   = (const float*)d_in[13];
    const float* b2   = (const float*)d_in[14];
    const float* ln1g = (const float*)d_in[15];
    const float* ln1b = (const float*)d_in[16];
    const float* ln2g = (const float*)d_in[17];
    const float* ln2b = (const float*)d_in[18];
    float* out = (float*)d_out;

    float *hb, *o1, *bqkv;
    bf16 *xnh, *xnl, *qkvh, *qkvl, *cxh, *cxl, *f1h, *f1l;
    bf16 *wqkvhp, *wqkvlp, *woh, *wol, *w1h, *w1l, *w2h, *w2l;
    cudaGetSymbolAddress((void**)&hb,   g_h);
    cudaGetSymbolAddress((void**)&o1,   g_out1);
    cudaGetSymbolAddress((void**)&bqkv, g_bqkv);
    cudaGetSymbolAddress((void**)&xnh,  g_xn_h);  cudaGetSymbolAddress((void**)&xnl, g_xn_l);
    cudaGetSymbolAddress((void**)&qkvh, g_qkv_h); cudaGetSymbolAddress((void**)&qkvl, g_qkv_l);
    cudaGetSymbolAddress((void**)&cxh,  g_ctx_h); cudaGetSymbolAddress((void**)&cxl, g_ctx_l);
    cudaGetSymbolAddress((void**)&f1h,  g_f1_h);  cudaGetSymbolAddress((void**)&f1l, g_f1_l);
    cudaGetSymbolAddress((void**)&wqkvhp, g_wqkvT_h); cudaGetSymbolAddress((void**)&wqkvlp, g_wqkvT_l);
    cudaGetSymbolAddress((void**)&woh,  g_woT_h); cudaGetSymbolAddress((void**)&wol, g_woT_l);
    cudaGetSymbolAddress((void**)&w1h,  g_w1T_h); cudaGetSymbolAddress((void**)&w1l, g_w1T_l);
    cudaGetSymbolAddress((void**)&w2h,  g_w2T_h); cudaGetSymbolAddress((void**)&w2l, g_w2T_l);

    cudaFuncSetAttribute(attn_mma_kernel, cudaFuncAttributeMaxDynamicSharedMemorySize, ATTN_SMEM);
    cudaFuncSetAttribute(gemm_mma_kernel, cudaFuncAttributeMaxDynamicSharedMemorySize, GEMM_SMEM);

    addpe_kernel<<<(M_ * D_) / 256, 256>>>(x, pe, hb);
    packb_kernel<<<dim3(D_ / 256, L_), 256>>>(bq, bk, bv, bqkv);
    {
        const size_t DD = (size_t)D_ * D_;
        dim3 gdd(D_ / 32, D_ / 32, L_);
        wtrans_kernel<<<gdd, 256>>>(wq, wqkvhp,          wqkvlp,          D_, D_, (size_t)D3 * D_);
        wtrans_kernel<<<gdd, 256>>>(wk, wqkvhp + DD,     wqkvlp + DD,     D_, D_, (size_t)D3 * D_);
        wtrans_kernel<<<gdd, 256>>>(wv, wqkvhp + 2 * DD, wqkvlp + 2 * DD, D_, D_, (size_t)D3 * D_);
        wtrans_kernel<<<gdd, 256>>>(wo, woh, wol, D_, D_, DD);
        dim3 g1(F_ / 32, D_ / 32, L_);
        wtrans_kernel<<<g1, 256>>>(w1, w1h, w1l, D_, F_, (size_t)D_ * F_);
        dim3 g2(D_ / 32, F_ / 32, L_);
        wtrans_kernel<<<g2, 256>>>(w2, w2h, w2l, F_, D_, (size_t)F_ * D_);
    }

    dim3 gQKV(D3 / 128, M_ / 128);   // (24, 64)
    dim3 gD(D_ / 128, M_ / 128);     // (8, 64)
    dim3 gF(F_ / 128, M_ / 128);     // (32, 64)
    dim3 gAttn(S_ / QT, H_, B_);

    for (int l = 0; l < L_; l++) {
        size_t oQKV = (size_t)l * D3 * D_;
        size_t oDD  = (size_t)l * D_ * D_;
        size_t oDF  = (size_t)l * D_ * F_;
        size_t oD   = (size_t)l * D_;
        size_t oF   = (size_t)l * F_;

        ln_kernel<<<M_, 256>>>(hb, ln1g + oD, ln1b + oD, xnh, xnl);
        gemm_mma_kernel<<<gQKV, 256, GEMM_SMEM>>>(xnh, xnl, wqkvhp + oQKV, wqkvlp + oQKV,
            bqkv + (size_t)l * D3, nullptr, nullptr, nullptr, qkvh, qkvl, D3, D_, 0);

        attn_mma_kernel<<<gAttn, 256, ATTN_SMEM>>>(qkvh, qkvl,
            bt + (size_t)l * (2 * P_ - 1) * H_, cxh, cxl);

        gemm_mma_kernel<<<gD, 256, GEMM_SMEM>>>(cxh, cxl, woh + oDD, wol + oDD,
            bo + oD, hb, nullptr, o1, nullptr, nullptr, D_, D_, 0);

        ln_kernel<<<M_, 256>>>(o1, ln2g + oD, ln2b + oD, xnh, xnl);
        gemm_mma_kernel<<<gF, 256, GEMM_SMEM>>>(xnh, xnl, w1h + oDF, w1l + oDF,
            b1 + oF, nullptr, nullptr, nullptr, f1h, f1l, F_, D_, 1);
        float* dst = (l == L_ - 1) ? out : hb;
        gemm_mma_kernel<<<gD, 256, GEMM_SMEM>>>(f1h, f1l, w2h + oDF, w2l + oDF,
            b2 + oD, o1, hb, dst, nullptr, nullptr, D_, F_, 0);
    }
}